// round 1
// baseline (speedup 1.0000x reference)
#include <cuda_runtime.h>
#include <math.h>

#define NTOK   4096
#define CDIM   768
#define QKVDIM 2304
#define FFDIM  3072
#define NEXP   8
#define CAP    1024
#define NPAIR  (NTOK*2)

__device__ float g_xln1[NTOK*CDIM];
__device__ float g_qkv [NTOK*QKVDIM];
__device__ float g_attn[NTOK*CDIM];
__device__ float g_x2  [NTOK*CDIM];
__device__ float g_xln2[NTOK*CDIM];
__device__ int   g_top_idx[NPAIR];
__device__ float g_top_w [NPAIR];
__device__ int   g_cnt[NEXP];
__device__ int   g_tok  [NEXP*CAP];
__device__ int   g_pairk[NEXP*CAP];
__device__ float g_wt   [NEXP*CAP];
__device__ float g_H    [NEXP*CAP*FFDIM];
__device__ float g_pair [NPAIR*CDIM];

__global__ void ln_kernel(const float* __restrict__ x,
                          const float* __restrict__ w,
                          float* __restrict__ y)
{
    const int row = blockIdx.x;
    const int tid = threadIdx.x;
    const float* xr = x + (size_t)row * CDIM;
    float v0 = xr[tid], v1 = xr[tid + 256], v2 = xr[tid + 512];
    float s = v0 + v1 + v2;
    float q = v0*v0 + v1*v1 + v2*v2;
    __shared__ float ss[256], sq[256];
    ss[tid] = s; sq[tid] = q;
    __syncthreads();
    for (int o = 128; o > 0; o >>= 1) {
        if (tid < o) { ss[tid] += ss[tid+o]; sq[tid] += sq[tid+o]; }
        __syncthreads();
    }
    const float mean = ss[0] * (1.f/768.f);
    const float var  = sq[0] * (1.f/768.f) - mean*mean;
    const float inv  = rsqrtf(var + 1e-5f);
    float* yr = y + (size_t)row * CDIM;
    yr[tid]       = (v0 - mean) * inv * w[tid];
    yr[tid + 256] = (v1 - mean) * inv * w[tid + 256];
    yr[tid + 512] = (v2 - mean) * inv * w[tid + 512];
}

__device__ __forceinline__ float gelu_f(float x) {
    return 0.5f * x * (1.0f + erff(x * 0.70710678118654752f));
}

template<int MODE>
__global__ void __launch_bounds__(256, 2) gemm_kernel(
    const float* __restrict__ A, const float* __restrict__ B,
    float* __restrict__ C, const float* __restrict__ res,
    int K, int N,
    const int* __restrict__ tokl, const float* __restrict__ wl,
    const int* __restrict__ pairk, const int* __restrict__ cnt)
{
    __shared__ float As[8][132];
    __shared__ float Bs[8][132];
    const int tid = threadIdx.x;
    const int n0 = blockIdx.x * 128;
    const int m0 = blockIdx.y * 128;
    const int e  = blockIdx.z;

    int mcount = 1 << 30;
    const float* Ab = A;
    const float* Bb = B;
    if (MODE >= 2) {
        mcount = cnt[e];
        if (m0 >= mcount) return;
        Bb = B + (size_t)e * K * N;
        if (MODE == 3) Ab = A + (size_t)e * CAP * K;
    }

    const int lm = tid >> 1;
    const int lh = (tid & 1) << 2;
    int  arow   = m0 + lm;
    bool avalid = true;
    if (MODE == 2) {
        avalid = (arow < mcount);
        arow   = avalid ? tokl[(e << 10) + (m0 + lm)] : 0;
    }
    const float* aP = Ab + (size_t)arow * K + lh;

    const float* bP;
    int bk = 0, bn4 = 0;
    if (MODE <= 1) {
        bP = Bb + (size_t)(n0 + lm) * K + lh;
    } else {
        bk = tid >> 5; bn4 = (tid & 31) << 2;
        bP = Bb + (size_t)bk * N + n0 + bn4;
    }

    float acc[8][8];
    #pragma unroll
    for (int i = 0; i < 8; i++)
        #pragma unroll
        for (int j = 0; j < 8; j++) acc[i][j] = 0.f;

    const int tx = tid & 15, ty = tid >> 4;

    for (int k0 = 0; k0 < K; k0 += 8) {
        float4 av = make_float4(0.f, 0.f, 0.f, 0.f);
        if (avalid) av = *(const float4*)(aP + k0);
        As[lh+0][lm] = av.x; As[lh+1][lm] = av.y;
        As[lh+2][lm] = av.z; As[lh+3][lm] = av.w;
        if (MODE <= 1) {
            float4 bv = *(const float4*)(bP + k0);
            Bs[lh+0][lm] = bv.x; Bs[lh+1][lm] = bv.y;
            Bs[lh+2][lm] = bv.z; Bs[lh+3][lm] = bv.w;
        } else {
            *(float4*)&Bs[bk][bn4] = *(const float4*)(bP + (size_t)k0 * N);
        }
        __syncthreads();
        #pragma unroll
        for (int k = 0; k < 8; k++) {
            float a[8], b[8];
            *(float4*)(a)   = *(const float4*)&As[k][ty*8];
            *(float4*)(a+4) = *(const float4*)&As[k][ty*8+4];
            *(float4*)(b)   = *(const float4*)&Bs[k][tx*8];
            *(float4*)(b+4) = *(const float4*)&Bs[k][tx*8+4];
            #pragma unroll
            for (int i = 0; i < 8; i++)
                #pragma unroll
                for (int j = 0; j < 8; j++)
                    acc[i][j] = fmaf(a[i], b[j], acc[i][j]);
        }
        __syncthreads();
    }

    if (MODE == 0) {
        #pragma unroll
        for (int i = 0; i < 8; i++) {
            float* cr = C + (size_t)(m0 + ty*8 + i) * N + n0 + tx*8;
            *(float4*)cr     = *(float4*)&acc[i][0];
            *(float4*)(cr+4) = *(float4*)&acc[i][4];
        }
    } else if (MODE == 1) {
        #pragma unroll
        for (int i = 0; i < 8; i++) {
            const size_t off = (size_t)(m0 + ty*8 + i) * N + n0 + tx*8;
            #pragma unroll
            for (int j = 0; j < 8; j++) C[off+j] = acc[i][j] + res[off+j];
        }
    } else if (MODE == 2) {
        float* Ce = C + (size_t)e * CAP * N;
        #pragma unroll
        for (int i = 0; i < 8; i++) {
            float* cr = Ce + (size_t)(m0 + ty*8 + i) * N + n0 + tx*8;
            float v[8];
            #pragma unroll
            for (int j = 0; j < 8; j++) v[j] = gelu_f(acc[i][j]);
            *(float4*)cr     = *(float4*)(v);
            *(float4*)(cr+4) = *(float4*)(v+4);
        }
    } else {
        #pragma unroll
        for (int i = 0; i < 8; i++) {
            const int r = m0 + ty*8 + i;
            if (r < mcount) {
                const int   t  = tokl [(e << 10) + r];
                const int   kk = pairk[(e << 10) + r];
                const float w  = wl   [(e << 10) + r];
                float* cr = C + (size_t)(t*2 + kk) * N + n0 + tx*8;
                #pragma unroll
                for (int j = 0; j < 8; j++) cr[j] = w * acc[i][j];
            }
        }
    }
}

__global__ void __launch_bounds__(64) attn_kernel(const float* __restrict__ qkv,
                                                  float* __restrict__ y)
{
    __shared__ float qs[64][68];
    __shared__ float ks[32][64];
    __shared__ float vs[32][64];
    const int qt  = blockIdx.x;
    const int h   = blockIdx.y;
    const int b   = blockIdx.z;
    const int tid = threadIdx.x;
    const int base = b * 2048;
    const int qcol = h * 64;

    for (int idx = tid; idx < 64*16; idx += 64) {
        const int r = idx >> 4, c4 = (idx & 15) * 4;
        float4 v = *(const float4*)&qkv[(size_t)(base + qt*64 + r)*QKVDIM + qcol + c4];
        v.x *= 0.125f; v.y *= 0.125f; v.z *= 0.125f; v.w *= 0.125f;
        *(float4*)&qs[r][c4] = v;
    }

    float4 o[16];
    #pragma unroll
    for (int i = 0; i < 16; i++) o[i] = make_float4(0.f, 0.f, 0.f, 0.f);
    float m = -INFINITY, l = 0.f;
    const int qg = qt*64 + tid;

    const int nkt = qt*2 + 2;
    for (int kt = 0; kt < nkt; kt++) {
        __syncthreads();
        for (int idx = tid; idx < 32*16; idx += 64) {
            const int r = idx >> 4, c4 = (idx & 15) * 4;
            const size_t rb = (size_t)(base + kt*32 + r) * QKVDIM + qcol;
            *(float4*)&ks[r][c4] = *(const float4*)&qkv[rb + 768  + c4];
            *(float4*)&vs[r][c4] = *(const float4*)&qkv[rb + 1536 + c4];
        }
        __syncthreads();
        const bool maskt = (kt >= qt*2);
        for (int ch = 0; ch < 2; ch++) {
            float s[16];
            #pragma unroll
            for (int j = 0; j < 16; j++) s[j] = 0.f;
            for (int d4 = 0; d4 < 16; d4++) {
                const float4 qv = *(const float4*)&qs[tid][d4*4];
                #pragma unroll
                for (int j = 0; j < 16; j++) {
                    const float4 kv = *(const float4*)&ks[ch*16 + j][d4*4];
                    s[j] = fmaf(qv.x, kv.x, fmaf(qv.y, kv.y,
                           fmaf(qv.z, kv.z, fmaf(qv.w, kv.w, s[j]))));
                }
            }
            float cmax = -INFINITY;
            #pragma unroll
            for (int j = 0; j < 16; j++) {
                if (maskt && (kt*32 + ch*16 + j > qg)) s[j] = -INFINITY;
                cmax = fmaxf(cmax, s[j]);
            }
            if (cmax == -INFINITY) continue;
            const float mn = fmaxf(m, cmax);
            const float scale = (m == -INFINITY) ? 0.f : __expf(m - mn);
            float ps = 0.f;
            #pragma unroll
            for (int j = 0; j < 16; j++) { s[j] = __expf(s[j] - mn); ps += s[j]; }
            l = l * scale + ps;
            #pragma unroll
            for (int d4 = 0; d4 < 16; d4++) {
                o[d4].x *= scale; o[d4].y *= scale;
                o[d4].z *= scale; o[d4].w *= scale;
            }
            #pragma unroll
            for (int j = 0; j < 16; j++) {
                const float p = s[j];
                #pragma unroll
                for (int d4 = 0; d4 < 16; d4++) {
                    const float4 vv = *(const float4*)&vs[ch*16 + j][d4*4];
                    o[d4].x = fmaf(p, vv.x, o[d4].x);
                    o[d4].y = fmaf(p, vv.y, o[d4].y);
                    o[d4].z = fmaf(p, vv.z, o[d4].z);
                    o[d4].w = fmaf(p, vv.w, o[d4].w);
                }
            }
            m = mn;
        }
    }
    const float inv = 1.f / l;
    #pragma unroll
    for (int d4 = 0; d4 < 16; d4++) {
        float4 v = o[d4];
        v.x *= inv; v.y *= inv; v.z *= inv; v.w *= inv;
        *(float4*)&y[(size_t)(base + qg)*CDIM + qcol + d4*4] = v;
    }
}

__global__ void router_kernel(const float* __restrict__ xln2,
                              const float* __restrict__ wg)
{
    __shared__ float wgs[NEXP*CDIM];
    const int tid = threadIdx.x;
    for (int i = tid; i < NEXP*CDIM; i += 256) wgs[i] = wg[i];
    __syncthreads();
    const int lane = tid & 31;
    const int t = blockIdx.x * 8 + (tid >> 5);
    const float* xr = xln2 + (size_t)t * CDIM;
    float xl[24];
    #pragma unroll
    for (int i = 0; i < 24; i++) xl[i] = xr[lane + (i << 5)];
    float lg[8];
    #pragma unroll
    for (int eo = 0; eo < 8; eo++) {
        float acc = 0.f;
        const float* wr = wgs + eo*CDIM;
        #pragma unroll
        for (int i = 0; i < 24; i++) acc = fmaf(xl[i], wr[lane + (i << 5)], acc);
        #pragma unroll
        for (int o = 16; o > 0; o >>= 1) acc += __shfl_down_sync(0xffffffffu, acc, o);
        lg[eo] = acc;
    }
    if (lane == 0) {
        int i1 = 0; float v1 = lg[0];
        #pragma unroll
        for (int eo = 1; eo < 8; eo++) if (lg[eo] > v1) { v1 = lg[eo]; i1 = eo; }
        int i2 = -1; float v2 = -INFINITY;
        #pragma unroll
        for (int eo = 0; eo < 8; eo++)
            if (eo != i1 && lg[eo] > v2) { v2 = lg[eo]; i2 = eo; }
        g_top_idx[t*2]   = i1;
        g_top_idx[t*2+1] = i2;
        g_top_w[t*2]     = 1.f / (1.f + __expf(v2 - v1));
        g_top_w[t*2+1]   = 1.f / (1.f + __expf(v1 - v2));
    }
}

__global__ void assign_kernel()
{
    const int e = threadIdx.x;
    if (e >= NEXP) return;
    int c = 0;
    #pragma unroll 8
    for (int p = 0; p < NPAIR; p++) {
        if (g_top_idx[p] == e) {
            if (c < CAP) {
                g_tok  [(e << 10) + c] = p >> 1;
                g_pairk[(e << 10) + c] = p & 1;
                g_wt   [(e << 10) + c] = g_top_w[p];
            }
            c++;
        }
    }
    g_cnt[e] = (c < CAP) ? c : CAP;
}

__global__ void zero_pair_kernel()
{
    const size_t i = (size_t)blockIdx.x * 256 + threadIdx.x;
    g_pair[i] = 0.f;
}

__global__ void combine_kernel(float* __restrict__ out)
{
    const int i = blockIdx.x * 256 + threadIdx.x;
    const int t = i / CDIM;
    const int c = i - t * CDIM;
    out[i] = g_x2[i] + g_pair[(size_t)(t*2)*CDIM + c]
                     + g_pair[(size_t)(t*2 + 1)*CDIM + c];
}

extern "C" void kernel_launch(void* const* d_in, const int* in_sizes, int n_in,
                              void* d_out, int out_size)
{
    const float* x      = (const float*)d_in[0];
    const float* ln1w   = (const float*)d_in[1];
    const float* ln2w   = (const float*)d_in[2];
    const float* cattn  = (const float*)d_in[3];
    const float* cproj  = (const float*)d_in[4];
    const float* wg     = (const float*)d_in[5];
    const float* cfc    = (const float*)d_in[6];
    const float* cproje = (const float*)d_in[7];
    float* out = (float*)d_out;

    float *xln1, *qkv, *attn, *x2, *xln2, *H, *pair, *wt;
    int *tok, *pairk, *cnt;
    cudaGetSymbolAddress((void**)&xln1,  g_xln1);
    cudaGetSymbolAddress((void**)&qkv,   g_qkv);
    cudaGetSymbolAddress((void**)&attn,  g_attn);
    cudaGetSymbolAddress((void**)&x2,    g_x2);
    cudaGetSymbolAddress((void**)&xln2,  g_xln2);
    cudaGetSymbolAddress((void**)&H,     g_H);
    cudaGetSymbolAddress((void**)&pair,  g_pair);
    cudaGetSymbolAddress((void**)&tok,   g_tok);
    cudaGetSymbolAddress((void**)&pairk, g_pairk);
    cudaGetSymbolAddress((void**)&cnt,   g_cnt);
    cudaGetSymbolAddress((void**)&wt,    g_wt);

    ln_kernel<<<NTOK, 256>>>(x, ln1w, xln1);
    gemm_kernel<0><<<dim3(QKVDIM/128, NTOK/128, 1), 256>>>(
        xln1, cattn, qkv, nullptr, CDIM, QKVDIM,
        nullptr, nullptr, nullptr, nullptr);
    attn_kernel<<<dim3(32, 12, 2), 64>>>(qkv, attn);
    gemm_kernel<1><<<dim3(CDIM/128, NTOK/128, 1), 256>>>(
        attn, cproj, x2, x, CDIM, CDIM,
        nullptr, nullptr, nullptr, nullptr);
    ln_kernel<<<NTOK, 256>>>(x2, ln2w, xln2);
    router_kernel<<<NTOK/8, 256>>>(xln2, wg);
    assign_kernel<<<1, 8>>>();
    gemm_kernel<2><<<dim3(FFDIM/128, CAP/128, NEXP), 256>>>(
        xln2, cfc, H, nullptr, CDIM, FFDIM,
        tok, wt, pairk, cnt);
    zero_pair_kernel<<<(NPAIR*CDIM)/256, 256>>>();
    gemm_kernel<3><<<dim3(CDIM/128, CAP/128, NEXP), 256>>>(
        H, cproje, pair, nullptr, FFDIM, CDIM,
        tok, wt, pairk, cnt);
    combine_kernel<<<(NTOK*CDIM)/256, 256>>>(out);
}

// round 2
// speedup vs baseline: 1.5264x; 1.5264x over previous
#include <cuda_runtime.h>
#include <math.h>
#include <stdint.h>

#define NTOK   4096
#define CDIM   768
#define QKVDIM 2304
#define FFDIM  3072
#define NEXP   8
#define CAP    1024
#define NPAIR  (NTOK*2)

__device__ float g_xln1[NTOK*CDIM];
__device__ float g_qkv [NTOK*QKVDIM];
__device__ float g_attn[NTOK*CDIM];
__device__ float g_x2  [NTOK*CDIM];
__device__ float g_xln2[NTOK*CDIM];
__device__ int   g_top_idx[NPAIR];
__device__ float g_top_w [NPAIR];
__device__ int   g_cnt[NEXP];
__device__ int   g_tok  [NEXP*CAP];
__device__ int   g_pairk[NEXP*CAP];
__device__ float g_wt   [NEXP*CAP];
__device__ float g_H    [NEXP*CAP*FFDIM];
__device__ float g_pair [NPAIR*CDIM];

// --------------------------------------------------------------------------
// LayerNorm
// --------------------------------------------------------------------------
__global__ void ln_kernel(const float* __restrict__ x,
                          const float* __restrict__ w,
                          float* __restrict__ y)
{
    const int row = blockIdx.x;
    const int tid = threadIdx.x;
    const float* xr = x + (size_t)row * CDIM;
    float v0 = xr[tid], v1 = xr[tid + 256], v2 = xr[tid + 512];
    float s = v0 + v1 + v2;
    float q = v0*v0 + v1*v1 + v2*v2;
    __shared__ float ss[256], sq[256];
    ss[tid] = s; sq[tid] = q;
    __syncthreads();
    for (int o = 128; o > 0; o >>= 1) {
        if (tid < o) { ss[tid] += ss[tid+o]; sq[tid] += sq[tid+o]; }
        __syncthreads();
    }
    const float mean = ss[0] * (1.f/768.f);
    const float var  = sq[0] * (1.f/768.f) - mean*mean;
    const float inv  = rsqrtf(var + 1e-5f);
    float* yr = y + (size_t)row * CDIM;
    yr[tid]       = (v0 - mean) * inv * w[tid];
    yr[tid + 256] = (v1 - mean) * inv * w[tid + 256];
    yr[tid + 512] = (v2 - mean) * inv * w[tid + 512];
}

__device__ __forceinline__ float gelu_f(float x) {
    return 0.5f * x * (1.0f + erff(x * 0.70710678118654752f));
}

__device__ __forceinline__ uint32_t f2tf32(float f) {
    uint32_t r;
    asm("cvt.rna.tf32.f32 %0, %1;" : "=r"(r) : "f"(f));
    return r;
}

__device__ __forceinline__ void mma_tf32(float* d, const uint32_t* a,
                                         const uint32_t* b) {
    asm volatile(
        "mma.sync.aligned.m16n8k8.row.col.f32.tf32.tf32.f32 "
        "{%0,%1,%2,%3}, {%4,%5,%6,%7}, {%8,%9}, {%0,%1,%2,%3};\n"
        : "+f"(d[0]), "+f"(d[1]), "+f"(d[2]), "+f"(d[3])
        : "r"(a[0]), "r"(a[1]), "r"(a[2]), "r"(a[3]),
          "r"(b[0]), "r"(b[1]));
}

// --------------------------------------------------------------------------
// TF32 tensor-core GEMM, 128x128x16 tiles, 8 warps x (64x32) warp tiles.
// MODE 0: QKV  C = A * W^T          (W row-major [N,K])
// MODE 1: PROJ C = A * W^T + res
// MODE 2: FC1  per-expert gathered rows, GELU epilogue -> H   (B is [K,N])
// MODE 3: FC2  per-expert A=H[e], scaled scatter -> g_pair    (B is [K,N])
// --------------------------------------------------------------------------
template<int MODE>
__global__ void __launch_bounds__(256, 2) gemm_tc_kernel(
    const float* __restrict__ A, const float* __restrict__ B,
    float* __restrict__ C, const float* __restrict__ res,
    int K, int N,
    const int* __restrict__ tokl, const float* __restrict__ wl,
    const int* __restrict__ pairk, const int* __restrict__ cnt)
{
    __shared__ uint32_t As[16][136];   // [k][m], pad 8 -> conflict-free frags
    __shared__ uint32_t Bs[16][136];   // [k][n]

    const int tid  = threadIdx.x;
    const int lane = tid & 31;
    const int wid  = tid >> 5;
    const int gid  = lane >> 2;        // 0..7
    const int tig  = lane & 3;         // 0..3
    const int wm   = wid & 1;          // 0..1 -> 64 rows
    const int wn   = wid >> 1;         // 0..3 -> 32 cols

    const int n0 = blockIdx.x * 128;
    const int m0 = blockIdx.y * 128;
    const int e  = blockIdx.z;

    int mcount = 1 << 30;
    const float* Ab = A;
    const float* Bb = B;
    if (MODE >= 2) {
        mcount = cnt[e];
        if (m0 >= mcount) return;
        Bb = B + (size_t)e * K * N;
        if (MODE == 3) Ab = A + (size_t)e * CAP * K;
    }

    // ---- A loader: thread -> row m0+lm, k = lkb..lkb+7 (2 x float4) ----
    const int lm  = tid >> 1;
    const int lkb = (tid & 1) << 3;
    int  arow   = m0 + lm;
    bool avalid = true;
    if (MODE == 2) {
        avalid = (arow < mcount);
        arow   = avalid ? tokl[(e << 10) + (m0 + lm)] : 0;
    }
    const float* aP = Ab + (size_t)arow * K + lkb;

    // ---- B loader ----
    const float* bP;
    int bk = 0, bnb = 0;
    if (MODE <= 1) {
        bP = Bb + (size_t)(n0 + lm) * K + lkb;            // transpose-load
    } else {
        bk = tid >> 4; bnb = (tid & 15) << 3;             // direct [K,N]
        bP = Bb + (size_t)bk * N + n0 + bnb;
    }

    float acc[4][4][4];
    #pragma unroll
    for (int mi = 0; mi < 4; mi++)
        #pragma unroll
        for (int ni = 0; ni < 4; ni++)
            #pragma unroll
            for (int r = 0; r < 4; r++) acc[mi][ni][r] = 0.f;

    for (int k0 = 0; k0 < K; k0 += 16) {
        // fill As
        {
            float4 v0 = make_float4(0.f,0.f,0.f,0.f), v1 = v0;
            if (avalid) {
                v0 = *(const float4*)(aP + k0);
                v1 = *(const float4*)(aP + k0 + 4);
            }
            As[lkb+0][lm] = f2tf32(v0.x); As[lkb+1][lm] = f2tf32(v0.y);
            As[lkb+2][lm] = f2tf32(v0.z); As[lkb+3][lm] = f2tf32(v0.w);
            As[lkb+4][lm] = f2tf32(v1.x); As[lkb+5][lm] = f2tf32(v1.y);
            As[lkb+6][lm] = f2tf32(v1.z); As[lkb+7][lm] = f2tf32(v1.w);
        }
        // fill Bs
        if (MODE <= 1) {
            float4 v0 = *(const float4*)(bP + k0);
            float4 v1 = *(const float4*)(bP + k0 + 4);
            Bs[lkb+0][lm] = f2tf32(v0.x); Bs[lkb+1][lm] = f2tf32(v0.y);
            Bs[lkb+2][lm] = f2tf32(v0.z); Bs[lkb+3][lm] = f2tf32(v0.w);
            Bs[lkb+4][lm] = f2tf32(v1.x); Bs[lkb+5][lm] = f2tf32(v1.y);
            Bs[lkb+6][lm] = f2tf32(v1.z); Bs[lkb+7][lm] = f2tf32(v1.w);
        } else {
            float4 v0 = *(const float4*)(bP + (size_t)k0 * N);
            float4 v1 = *(const float4*)(bP + (size_t)k0 * N + 4);
            Bs[bk][bnb+0] = f2tf32(v0.x); Bs[bk][bnb+1] = f2tf32(v0.y);
            Bs[bk][bnb+2] = f2tf32(v0.z); Bs[bk][bnb+3] = f2tf32(v0.w);
            Bs[bk][bnb+4] = f2tf32(v1.x); Bs[bk][bnb+5] = f2tf32(v1.y);
            Bs[bk][bnb+6] = f2tf32(v1.z); Bs[bk][bnb+7] = f2tf32(v1.w);
        }
        __syncthreads();

        #pragma unroll
        for (int ks = 0; ks < 16; ks += 8) {
            uint32_t af[4][4], bf[4][2];
            #pragma unroll
            for (int mi = 0; mi < 4; mi++) {
                const int rb = wm*64 + mi*16;
                af[mi][0] = As[ks + tig    ][rb + gid    ];
                af[mi][1] = As[ks + tig    ][rb + gid + 8];
                af[mi][2] = As[ks + tig + 4][rb + gid    ];
                af[mi][3] = As[ks + tig + 4][rb + gid + 8];
            }
            #pragma unroll
            for (int ni = 0; ni < 4; ni++) {
                const int cb = wn*32 + ni*8;
                bf[ni][0] = Bs[ks + tig    ][cb + gid];
                bf[ni][1] = Bs[ks + tig + 4][cb + gid];
            }
            #pragma unroll
            for (int mi = 0; mi < 4; mi++)
                #pragma unroll
                for (int ni = 0; ni < 4; ni++)
                    mma_tf32(acc[mi][ni], af[mi], bf[ni]);
        }
        __syncthreads();
    }

    // ---- epilogue ----
    // acc[mi][ni][{0,1}] -> row r1 = wm*64+mi*16+gid,   cols c, c+1
    // acc[mi][ni][{2,3}] -> row r2 = r1 + 8,            cols c, c+1
    // c = wn*32 + ni*8 + tig*2
    #pragma unroll
    for (int mi = 0; mi < 4; mi++) {
        const int r1 = wm*64 + mi*16 + gid;
        const int r2 = r1 + 8;
        if (MODE == 0) {
            #pragma unroll
            for (int ni = 0; ni < 4; ni++) {
                const int c = wn*32 + ni*8 + tig*2;
                *(float2*)&C[(size_t)(m0 + r1) * N + n0 + c] =
                    make_float2(acc[mi][ni][0], acc[mi][ni][1]);
                *(float2*)&C[(size_t)(m0 + r2) * N + n0 + c] =
                    make_float2(acc[mi][ni][2], acc[mi][ni][3]);
            }
        } else if (MODE == 1) {
            #pragma unroll
            for (int ni = 0; ni < 4; ni++) {
                const int c = wn*32 + ni*8 + tig*2;
                const size_t o1 = (size_t)(m0 + r1) * N + n0 + c;
                const size_t o2 = (size_t)(m0 + r2) * N + n0 + c;
                const float2 q1 = *(const float2*)&res[o1];
                const float2 q2 = *(const float2*)&res[o2];
                *(float2*)&C[o1] = make_float2(acc[mi][ni][0] + q1.x,
                                               acc[mi][ni][1] + q1.y);
                *(float2*)&C[o2] = make_float2(acc[mi][ni][2] + q2.x,
                                               acc[mi][ni][3] + q2.y);
            }
        } else if (MODE == 2) {
            float* Ce = C + (size_t)e * CAP * N;
            #pragma unroll
            for (int ni = 0; ni < 4; ni++) {
                const int c = wn*32 + ni*8 + tig*2;
                *(float2*)&Ce[(size_t)(m0 + r1) * N + n0 + c] =
                    make_float2(gelu_f(acc[mi][ni][0]), gelu_f(acc[mi][ni][1]));
                *(float2*)&Ce[(size_t)(m0 + r2) * N + n0 + c] =
                    make_float2(gelu_f(acc[mi][ni][2]), gelu_f(acc[mi][ni][3]));
            }
        } else {
            const bool v1 = (m0 + r1) < mcount;
            const bool v2 = (m0 + r2) < mcount;
            int   t1 = 0, k1 = 0, t2 = 0, k2 = 0;
            float w1 = 0.f, w2 = 0.f;
            if (v1) {
                t1 = tokl [(e << 10) + m0 + r1];
                k1 = pairk[(e << 10) + m0 + r1];
                w1 = wl   [(e << 10) + m0 + r1];
            }
            if (v2) {
                t2 = tokl [(e << 10) + m0 + r2];
                k2 = pairk[(e << 10) + m0 + r2];
                w2 = wl   [(e << 10) + m0 + r2];
            }
            #pragma unroll
            for (int ni = 0; ni < 4; ni++) {
                const int c = wn*32 + ni*8 + tig*2;
                if (v1)
                    *(float2*)&C[(size_t)(t1*2 + k1) * N + n0 + c] =
                        make_float2(w1 * acc[mi][ni][0], w1 * acc[mi][ni][1]);
                if (v2)
                    *(float2*)&C[(size_t)(t2*2 + k2) * N + n0 + c] =
                        make_float2(w2 * acc[mi][ni][2], w2 * acc[mi][ni][3]);
            }
        }
    }
}

// --------------------------------------------------------------------------
// Flash attention (causal, D=64) - fp32 (unchanged this round)
// --------------------------------------------------------------------------
__global__ void __launch_bounds__(64) attn_kernel(const float* __restrict__ qkv,
                                                  float* __restrict__ y)
{
    __shared__ float qs[64][68];
    __shared__ float ks[32][64];
    __shared__ float vs[32][64];
    const int qt  = blockIdx.x;
    const int h   = blockIdx.y;
    const int b   = blockIdx.z;
    const int tid = threadIdx.x;
    const int base = b * 2048;
    const int qcol = h * 64;

    for (int idx = tid; idx < 64*16; idx += 64) {
        const int r = idx >> 4, c4 = (idx & 15) * 4;
        float4 v = *(const float4*)&qkv[(size_t)(base + qt*64 + r)*QKVDIM + qcol + c4];
        v.x *= 0.125f; v.y *= 0.125f; v.z *= 0.125f; v.w *= 0.125f;
        *(float4*)&qs[r][c4] = v;
    }

    float4 o[16];
    #pragma unroll
    for (int i = 0; i < 16; i++) o[i] = make_float4(0.f, 0.f, 0.f, 0.f);
    float m = -INFINITY, l = 0.f;
    const int qg = qt*64 + tid;

    const int nkt = qt*2 + 2;
    for (int kt = 0; kt < nkt; kt++) {
        __syncthreads();
        for (int idx = tid; idx < 32*16; idx += 64) {
            const int r = idx >> 4, c4 = (idx & 15) * 4;
            const size_t rb = (size_t)(base + kt*32 + r) * QKVDIM + qcol;
            *(float4*)&ks[r][c4] = *(const float4*)&qkv[rb + 768  + c4];
            *(float4*)&vs[r][c4] = *(const float4*)&qkv[rb + 1536 + c4];
        }
        __syncthreads();
        const bool maskt = (kt >= qt*2);
        for (int ch = 0; ch < 2; ch++) {
            float s[16];
            #pragma unroll
            for (int j = 0; j < 16; j++) s[j] = 0.f;
            for (int d4 = 0; d4 < 16; d4++) {
                const float4 qv = *(const float4*)&qs[tid][d4*4];
                #pragma unroll
                for (int j = 0; j < 16; j++) {
                    const float4 kv = *(const float4*)&ks[ch*16 + j][d4*4];
                    s[j] = fmaf(qv.x, kv.x, fmaf(qv.y, kv.y,
                           fmaf(qv.z, kv.z, fmaf(qv.w, kv.w, s[j]))));
                }
            }
            float cmax = -INFINITY;
            #pragma unroll
            for (int j = 0; j < 16; j++) {
                if (maskt && (kt*32 + ch*16 + j > qg)) s[j] = -INFINITY;
                cmax = fmaxf(cmax, s[j]);
            }
            if (cmax == -INFINITY) continue;
            const float mn = fmaxf(m, cmax);
            const float scale = (m == -INFINITY) ? 0.f : __expf(m - mn);
            float ps = 0.f;
            #pragma unroll
            for (int j = 0; j < 16; j++) { s[j] = __expf(s[j] - mn); ps += s[j]; }
            l = l * scale + ps;
            #pragma unroll
            for (int d4 = 0; d4 < 16; d4++) {
                o[d4].x *= scale; o[d4].y *= scale;
                o[d4].z *= scale; o[d4].w *= scale;
            }
            #pragma unroll
            for (int j = 0; j < 16; j++) {
                const float p = s[j];
                #pragma unroll
                for (int d4 = 0; d4 < 16; d4++) {
                    const float4 vv = *(const float4*)&vs[ch*16 + j][d4*4];
                    o[d4].x = fmaf(p, vv.x, o[d4].x);
                    o[d4].y = fmaf(p, vv.y, o[d4].y);
                    o[d4].z = fmaf(p, vv.z, o[d4].z);
                    o[d4].w = fmaf(p, vv.w, o[d4].w);
                }
            }
            m = mn;
        }
    }
    const float inv = 1.f / l;
    #pragma unroll
    for (int d4 = 0; d4 < 16; d4++) {
        float4 v = o[d4];
        v.x *= inv; v.y *= inv; v.z *= inv; v.w *= inv;
        *(float4*)&y[(size_t)(base + qg)*CDIM + qcol + d4*4] = v;
    }
}

// --------------------------------------------------------------------------
// Router / assignment / combine
// --------------------------------------------------------------------------
__global__ void router_kernel(const float* __restrict__ xln2,
                              const float* __restrict__ wg)
{
    __shared__ float wgs[NEXP*CDIM];
    const int tid = threadIdx.x;
    for (int i = tid; i < NEXP*CDIM; i += 256) wgs[i] = wg[i];
    __syncthreads();
    const int lane = tid & 31;
    const int t = blockIdx.x * 8 + (tid >> 5);
    const float* xr = xln2 + (size_t)t * CDIM;
    float xl[24];
    #pragma unroll
    for (int i = 0; i < 24; i++) xl[i] = xr[lane + (i << 5)];
    float lg[8];
    #pragma unroll
    for (int eo = 0; eo < 8; eo++) {
        float acc = 0.f;
        const float* wr = wgs + eo*CDIM;
        #pragma unroll
        for (int i = 0; i < 24; i++) acc = fmaf(xl[i], wr[lane + (i << 5)], acc);
        #pragma unroll
        for (int o = 16; o > 0; o >>= 1) acc += __shfl_down_sync(0xffffffffu, acc, o);
        lg[eo] = acc;
    }
    if (lane == 0) {
        int i1 = 0; float v1 = lg[0];
        #pragma unroll
        for (int eo = 1; eo < 8; eo++) if (lg[eo] > v1) { v1 = lg[eo]; i1 = eo; }
        int i2 = -1; float v2 = -INFINITY;
        #pragma unroll
        for (int eo = 0; eo < 8; eo++)
            if (eo != i1 && lg[eo] > v2) { v2 = lg[eo]; i2 = eo; }
        g_top_idx[t*2]   = i1;
        g_top_idx[t*2+1] = i2;
        g_top_w[t*2]     = 1.f / (1.f + __expf(v2 - v1));
        g_top_w[t*2+1]   = 1.f / (1.f + __expf(v1 - v2));
    }
}

__global__ void assign_kernel()
{
    const int e = threadIdx.x;
    if (e >= NEXP) return;
    int c = 0;
    #pragma unroll 8
    for (int p = 0; p < NPAIR; p++) {
        if (g_top_idx[p] == e) {
            if (c < CAP) {
                g_tok  [(e << 10) + c] = p >> 1;
                g_pairk[(e << 10) + c] = p & 1;
                g_wt   [(e << 10) + c] = g_top_w[p];
            }
            c++;
        }
    }
    g_cnt[e] = (c < CAP) ? c : CAP;
}

__global__ void zero_pair_kernel()
{
    const size_t i = (size_t)blockIdx.x * 256 + threadIdx.x;
    g_pair[i] = 0.f;
}

__global__ void combine_kernel(float* __restrict__ out)
{
    const int i = blockIdx.x * 256 + threadIdx.x;
    const int t = i / CDIM;
    const int c = i - t * CDIM;
    out[i] = g_x2[i] + g_pair[(size_t)(t*2)*CDIM + c]
                     + g_pair[(size_t)(t*2 + 1)*CDIM + c];
}

// --------------------------------------------------------------------------
extern "C" void kernel_launch(void* const* d_in, const int* in_sizes, int n_in,
                              void* d_out, int out_size)
{
    const float* x      = (const float*)d_in[0];
    const float* ln1w   = (const float*)d_in[1];
    const float* ln2w   = (const float*)d_in[2];
    const float* cattn  = (const float*)d_in[3];
    const float* cproj  = (const float*)d_in[4];
    const float* wg     = (const float*)d_in[5];
    const float* cfc    = (const float*)d_in[6];
    const float* cproje = (const float*)d_in[7];
    float* out = (float*)d_out;

    float *xln1, *qkv, *attn, *x2, *xln2, *H, *pair, *wt;
    int *tok, *pairk, *cnt;
    cudaGetSymbolAddress((void**)&xln1,  g_xln1);
    cudaGetSymbolAddress((void**)&qkv,   g_qkv);
    cudaGetSymbolAddress((void**)&attn,  g_attn);
    cudaGetSymbolAddress((void**)&x2,    g_x2);
    cudaGetSymbolAddress((void**)&xln2,  g_xln2);
    cudaGetSymbolAddress((void**)&H,     g_H);
    cudaGetSymbolAddress((void**)&pair,  g_pair);
    cudaGetSymbolAddress((void**)&tok,   g_tok);
    cudaGetSymbolAddress((void**)&pairk, g_pairk);
    cudaGetSymbolAddress((void**)&cnt,   g_cnt);
    cudaGetSymbolAddress((void**)&wt,    g_wt);

    ln_kernel<<<NTOK, 256>>>(x, ln1w, xln1);
    gemm_tc_kernel<0><<<dim3(QKVDIM/128, NTOK/128, 1), 256>>>(
        xln1, cattn, qkv, nullptr, CDIM, QKVDIM,
        nullptr, nullptr, nullptr, nullptr);
    attn_kernel<<<dim3(32, 12, 2), 64>>>(qkv, attn);
    gemm_tc_kernel<1><<<dim3(CDIM/128, NTOK/128, 1), 256>>>(
        attn, cproj, x2, x, CDIM, CDIM,
        nullptr, nullptr, nullptr, nullptr);
    ln_kernel<<<NTOK, 256>>>(x2, ln2w, xln2);
    router_kernel<<<NTOK/8, 256>>>(xln2, wg);
    assign_kernel<<<1, 8>>>();
    gemm_tc_kernel<2><<<dim3(FFDIM/128, CAP/128, NEXP), 256>>>(
        xln2, cfc, H, nullptr, CDIM, FFDIM,
        tok, wt, pairk, cnt);
    zero_pair_kernel<<<(NPAIR*CDIM)/256, 256>>>();
    gemm_tc_kernel<3><<<dim3(CDIM/128, CAP/128, NEXP), 256>>>(
        H, cproje, pair, nullptr, FFDIM, CDIM,
        tok, wt, pairk, cnt);
    combine_kernel<<<(NTOK*CDIM)/256, 256>>>(out);
}

// round 3
// speedup vs baseline: 3.4092x; 2.2335x over previous
#include <cuda_runtime.h>
#include <math.h>
#include <stdint.h>

#define NTOK   4096
#define CDIM   768
#define QKVDIM 2304
#define FFDIM  3072
#define NEXP   8
#define CAP    1024
#define NPAIR  (NTOK*2)

__device__ float g_xln1[NTOK*CDIM];
__device__ float g_qkv [NTOK*QKVDIM];
__device__ float g_attn[NTOK*CDIM];
__device__ float g_x2  [NTOK*CDIM];
__device__ float g_xln2[NTOK*CDIM];
__device__ int   g_top_idx[NPAIR];
__device__ float g_top_w [NPAIR];
__device__ int   g_cnt[NEXP];
__device__ int   g_tok  [NEXP*CAP];
__device__ int   g_pairk[NEXP*CAP];
__device__ float g_wt   [NEXP*CAP];
__device__ float g_H    [NEXP*CAP*FFDIM];
__device__ float g_pair [NPAIR*CDIM];

// --------------------------------------------------------------------------
// helpers
// --------------------------------------------------------------------------
__device__ __forceinline__ float gelu_f(float x) {
    return 0.5f * x * (1.0f + erff(x * 0.70710678118654752f));
}
__device__ __forceinline__ uint32_t f2tf32(float f) {
    uint32_t r;
    asm("cvt.rna.tf32.f32 %0, %1;" : "=r"(r) : "f"(f));
    return r;
}
__device__ __forceinline__ void mma_tf32(float* d, const uint32_t* a,
                                         const uint32_t* b) {
    asm volatile(
        "mma.sync.aligned.m16n8k8.row.col.f32.tf32.tf32.f32 "
        "{%0,%1,%2,%3}, {%4,%5,%6,%7}, {%8,%9}, {%0,%1,%2,%3};\n"
        : "+f"(d[0]), "+f"(d[1]), "+f"(d[2]), "+f"(d[3])
        : "r"(a[0]), "r"(a[1]), "r"(a[2]), "r"(a[3]),
          "r"(b[0]), "r"(b[1]));
}
__device__ __forceinline__ uint32_t smem_u32(const void* p) {
    return (uint32_t)__cvta_generic_to_shared(p);
}
__device__ __forceinline__ void cp16(uint32_t dst, const void* src, int bytes) {
    asm volatile("cp.async.cg.shared.global [%0], [%1], 16, %2;\n"
                 :: "r"(dst), "l"(src), "r"(bytes));
}
#define CP_COMMIT() asm volatile("cp.async.commit_group;\n" ::: "memory")
#define CP_WAIT1()  asm volatile("cp.async.wait_group 1;\n" ::: "memory")

// --------------------------------------------------------------------------
// LayerNorm
// --------------------------------------------------------------------------
__global__ void ln_kernel(const float* __restrict__ x,
                          const float* __restrict__ w,
                          float* __restrict__ y)
{
    const int row = blockIdx.x;
    const int tid = threadIdx.x;
    const float* xr = x + (size_t)row * CDIM;
    float v0 = xr[tid], v1 = xr[tid + 256], v2 = xr[tid + 512];
    float s = v0 + v1 + v2;
    float q = v0*v0 + v1*v1 + v2*v2;
    __shared__ float ss[256], sq[256];
    ss[tid] = s; sq[tid] = q;
    __syncthreads();
    for (int o = 128; o > 0; o >>= 1) {
        if (tid < o) { ss[tid] += ss[tid+o]; sq[tid] += sq[tid+o]; }
        __syncthreads();
    }
    const float mean = ss[0] * (1.f/768.f);
    const float var  = sq[0] * (1.f/768.f) - mean*mean;
    const float inv  = rsqrtf(var + 1e-5f);
    float* yr = y + (size_t)row * CDIM;
    yr[tid]       = (v0 - mean) * inv * w[tid];
    yr[tid + 256] = (v1 - mean) * inv * w[tid + 256];
    yr[tid + 512] = (v2 - mean) * inv * w[tid + 512];
}

// --------------------------------------------------------------------------
// TF32 tensor-core GEMM, cp.async double-buffered, 128x128x16 tiles.
// MODE 0: QKV  C = A*W^T      MODE 1: PROJ C = A*W^T + res
// MODE 2: FC1  gathered rows, GELU -> H (B row-major [K,N])
// MODE 3: FC2  A=H[e], scaled scatter -> g_pair (B row-major [K,N])
// --------------------------------------------------------------------------
template<int MODE>
__global__ void __launch_bounds__(256, 2) gemm_tc_kernel(
    const float* __restrict__ A, const float* __restrict__ B,
    float* __restrict__ C, const float* __restrict__ res,
    int K, int N,
    const int* __restrict__ tokl, const float* __restrict__ wl,
    const int* __restrict__ pairk, const int* __restrict__ cnt)
{
    constexpr int BR = (MODE <= 1) ? 128 : 16;
    constexpr int BC = (MODE <= 1) ? 20  : 132;
    __shared__ float As[2][128][20];     // [m][k], stride 20 -> conflict-free
    __shared__ float Bs[2][BR][BC];      // mode<=1: [n][k]; mode>=2: [k][n]

    const int tid  = threadIdx.x;
    const int lane = tid & 31;
    const int wid  = tid >> 5;
    const int gid  = lane >> 2;
    const int tig  = lane & 3;
    const int wm   = wid & 1;
    const int wn   = wid >> 1;

    const int n0 = blockIdx.x * 128;
    const int m0 = blockIdx.y * 128;
    const int e  = blockIdx.z;

    int mcount = 1 << 30;
    const float* Ab = A;
    const float* Bb = B;
    if (MODE >= 2) {
        mcount = cnt[e];
        if (m0 >= mcount) return;
        Bb = B + (size_t)e * K * N;
        if (MODE == 3) Ab = A + (size_t)e * CAP * K;
    }

    // A loader: row lm = tid>>1, k cols lkb..lkb+7
    const int lm  = tid >> 1;
    const int lkb = (tid & 1) << 3;
    int  arow   = m0 + lm;
    int  abytes = 16;
    if (MODE == 2) {
        const bool av = (arow < mcount);
        arow   = av ? tokl[(e << 10) + (m0 + lm)] : 0;
        abytes = av ? 16 : 0;
    }
    const float* aP = Ab + (size_t)arow * K + lkb;

    // B loader
    const float* bP;
    int bk = 0, bnb = 0;
    if (MODE <= 1) {
        bP = Bb + (size_t)(n0 + lm) * K + lkb;
    } else {
        bk = tid >> 4; bnb = (tid & 15) << 3;
        bP = Bb + (size_t)bk * N + n0 + bnb;
    }

    float acc[4][4][4];
    #pragma unroll
    for (int mi = 0; mi < 4; mi++)
        #pragma unroll
        for (int ni = 0; ni < 4; ni++)
            #pragma unroll
            for (int r = 0; r < 4; r++) acc[mi][ni][r] = 0.f;

    auto load_stage = [&](int stg, int k0) {
        uint32_t ad = smem_u32(&As[stg][lm][lkb]);
        cp16(ad,      aP + k0,     abytes);
        cp16(ad + 16, aP + k0 + 4, abytes);
        if (MODE <= 1) {
            uint32_t bd = smem_u32(&Bs[stg][lm][lkb]);
            cp16(bd,      bP + k0,     16);
            cp16(bd + 16, bP + k0 + 4, 16);
        } else {
            uint32_t bd = smem_u32(&Bs[stg][bk][bnb]);
            const float* src = bP + (size_t)k0 * N;
            cp16(bd,      src,     16);
            cp16(bd + 16, src + 4, 16);
        }
    };

    load_stage(0, 0);
    CP_COMMIT();

    int stg = 0;
    for (int k0 = 0; k0 < K; k0 += 16) {
        if (k0 + 16 < K) load_stage(stg ^ 1, k0 + 16);
        CP_COMMIT();
        CP_WAIT1();
        __syncthreads();

        #pragma unroll
        for (int ks = 0; ks < 16; ks += 8) {
            uint32_t af[4][4], bf[4][2];
            #pragma unroll
            for (int mi = 0; mi < 4; mi++) {
                const int rb = wm*64 + mi*16;
                af[mi][0] = __float_as_uint(As[stg][rb + gid    ][ks + tig    ]);
                af[mi][1] = __float_as_uint(As[stg][rb + gid + 8][ks + tig    ]);
                af[mi][2] = __float_as_uint(As[stg][rb + gid    ][ks + tig + 4]);
                af[mi][3] = __float_as_uint(As[stg][rb + gid + 8][ks + tig + 4]);
            }
            #pragma unroll
            for (int ni = 0; ni < 4; ni++) {
                const int cb = wn*32 + ni*8;
                if (MODE <= 1) {
                    bf[ni][0] = __float_as_uint(Bs[stg][cb + gid][ks + tig    ]);
                    bf[ni][1] = __float_as_uint(Bs[stg][cb + gid][ks + tig + 4]);
                } else {
                    bf[ni][0] = __float_as_uint(Bs[stg][ks + tig    ][cb + gid]);
                    bf[ni][1] = __float_as_uint(Bs[stg][ks + tig + 4][cb + gid]);
                }
            }
            #pragma unroll
            for (int mi = 0; mi < 4; mi++)
                #pragma unroll
                for (int ni = 0; ni < 4; ni++)
                    mma_tf32(acc[mi][ni], af[mi], bf[ni]);
        }
        stg ^= 1;
        __syncthreads();
    }

    // ---- epilogue ----
    #pragma unroll
    for (int mi = 0; mi < 4; mi++) {
        const int r1 = wm*64 + mi*16 + gid;
        const int r2 = r1 + 8;
        if (MODE == 0) {
            #pragma unroll
            for (int ni = 0; ni < 4; ni++) {
                const int c = wn*32 + ni*8 + tig*2;
                *(float2*)&C[(size_t)(m0 + r1) * N + n0 + c] =
                    make_float2(acc[mi][ni][0], acc[mi][ni][1]);
                *(float2*)&C[(size_t)(m0 + r2) * N + n0 + c] =
                    make_float2(acc[mi][ni][2], acc[mi][ni][3]);
            }
        } else if (MODE == 1) {
            #pragma unroll
            for (int ni = 0; ni < 4; ni++) {
                const int c = wn*32 + ni*8 + tig*2;
                const size_t o1 = (size_t)(m0 + r1) * N + n0 + c;
                const size_t o2 = (size_t)(m0 + r2) * N + n0 + c;
                const float2 q1 = *(const float2*)&res[o1];
                const float2 q2 = *(const float2*)&res[o2];
                *(float2*)&C[o1] = make_float2(acc[mi][ni][0] + q1.x,
                                               acc[mi][ni][1] + q1.y);
                *(float2*)&C[o2] = make_float2(acc[mi][ni][2] + q2.x,
                                               acc[mi][ni][3] + q2.y);
            }
        } else if (MODE == 2) {
            float* Ce = C + (size_t)e * CAP * N;
            #pragma unroll
            for (int ni = 0; ni < 4; ni++) {
                const int c = wn*32 + ni*8 + tig*2;
                *(float2*)&Ce[(size_t)(m0 + r1) * N + n0 + c] =
                    make_float2(gelu_f(acc[mi][ni][0]), gelu_f(acc[mi][ni][1]));
                *(float2*)&Ce[(size_t)(m0 + r2) * N + n0 + c] =
                    make_float2(gelu_f(acc[mi][ni][2]), gelu_f(acc[mi][ni][3]));
            }
        } else {
            const bool v1 = (m0 + r1) < mcount;
            const bool v2 = (m0 + r2) < mcount;
            int   t1 = 0, k1 = 0, t2 = 0, k2 = 0;
            float w1 = 0.f, w2 = 0.f;
            if (v1) {
                t1 = tokl [(e << 10) + m0 + r1];
                k1 = pairk[(e << 10) + m0 + r1];
                w1 = wl   [(e << 10) + m0 + r1];
            }
            if (v2) {
                t2 = tokl [(e << 10) + m0 + r2];
                k2 = pairk[(e << 10) + m0 + r2];
                w2 = wl   [(e << 10) + m0 + r2];
            }
            #pragma unroll
            for (int ni = 0; ni < 4; ni++) {
                const int c = wn*32 + ni*8 + tig*2;
                if (v1)
                    *(float2*)&C[(size_t)(t1*2 + k1) * N + n0 + c] =
                        make_float2(w1 * acc[mi][ni][0], w1 * acc[mi][ni][1]);
                if (v2)
                    *(float2*)&C[(size_t)(t2*2 + k2) * N + n0 + c] =
                        make_float2(w2 * acc[mi][ni][2], w2 * acc[mi][ni][3]);
            }
        }
    }
}

// --------------------------------------------------------------------------
// Tensor-core flash attention (causal, D=64), tf32 mma.
// Block: 64 q-rows x (head,batch); 4 warps, warp w owns q-rows w*16..w*16+15.
// --------------------------------------------------------------------------
__global__ void __launch_bounds__(128) attn_tc_kernel(
    const float* __restrict__ qkv, float* __restrict__ y)
{
    __shared__ float qs[64][68];      // [q][d]   stride 68 -> frag-load clean
    __shared__ float ks[32][68];      // [key][d]
    __shared__ float vs[32][72];      // [key][d] stride 72 -> B-frag clean
    __shared__ float ps[4][16][36];   // per-warp P tile [m][k]

    const int qt  = blockIdx.x;
    const int h   = blockIdx.y;
    const int b   = blockIdx.z;
    const int tid  = threadIdx.x;
    const int lane = tid & 31;
    const int w    = tid >> 5;
    const int gid  = lane >> 2;
    const int tig  = lane & 3;
    const int base = b * 2048;
    const int qcol = h * 64;

    // load + prescale + tf32-round Q tile
    for (int idx = tid; idx < 64*16; idx += 128) {
        const int r = idx >> 4, c4 = (idx & 15) << 2;
        float4 v = *(const float4*)&qkv[(size_t)(base + qt*64 + r)*QKVDIM + qcol + c4];
        qs[r][c4+0] = __uint_as_float(f2tf32(v.x * 0.125f));
        qs[r][c4+1] = __uint_as_float(f2tf32(v.y * 0.125f));
        qs[r][c4+2] = __uint_as_float(f2tf32(v.z * 0.125f));
        qs[r][c4+3] = __uint_as_float(f2tf32(v.w * 0.125f));
    }

    float o[8][4];
    #pragma unroll
    for (int i = 0; i < 8; i++)
        #pragma unroll
        for (int r = 0; r < 4; r++) o[i][r] = 0.f;
    float m0r = -INFINITY, m1r = -INFINITY, l0 = 0.f, l1 = 0.f;

    const int warp_max_row = qt*64 + w*16 + 15;    // global q row max of warp
    const int nkt = qt*2 + 2;

    for (int kt = 0; kt < nkt; kt++) {
        __syncthreads();
        for (int idx = tid; idx < 32*16; idx += 128) {
            const int r = idx >> 4, c4 = (idx & 15) << 2;
            const size_t rb = (size_t)(base + kt*32 + r) * QKVDIM + qcol;
            float4 kv = *(const float4*)&qkv[rb + 768  + c4];
            float4 vv = *(const float4*)&qkv[rb + 1536 + c4];
            ks[r][c4+0] = __uint_as_float(f2tf32(kv.x));
            ks[r][c4+1] = __uint_as_float(f2tf32(kv.y));
            ks[r][c4+2] = __uint_as_float(f2tf32(kv.z));
            ks[r][c4+3] = __uint_as_float(f2tf32(kv.w));
            vs[r][c4+0] = __uint_as_float(f2tf32(vv.x));
            vs[r][c4+1] = __uint_as_float(f2tf32(vv.y));
            vs[r][c4+2] = __uint_as_float(f2tf32(vv.z));
            vs[r][c4+3] = __uint_as_float(f2tf32(vv.w));
        }
        __syncthreads();
        if (kt*32 > warp_max_row) continue;   // tile fully above warp's rows

        // ---- S = Q K^T : m16 n32 k64 ----
        float s[4][4];
        #pragma unroll
        for (int ni = 0; ni < 4; ni++)
            #pragma unroll
            for (int r = 0; r < 4; r++) s[ni][r] = 0.f;
        #pragma unroll
        for (int k8 = 0; k8 < 64; k8 += 8) {
            uint32_t af[4], bf[4][2];
            af[0] = __float_as_uint(qs[w*16 + gid    ][k8 + tig    ]);
            af[1] = __float_as_uint(qs[w*16 + gid + 8][k8 + tig    ]);
            af[2] = __float_as_uint(qs[w*16 + gid    ][k8 + tig + 4]);
            af[3] = __float_as_uint(qs[w*16 + gid + 8][k8 + tig + 4]);
            #pragma unroll
            for (int ni = 0; ni < 4; ni++) {
                bf[ni][0] = __float_as_uint(ks[ni*8 + gid][k8 + tig    ]);
                bf[ni][1] = __float_as_uint(ks[ni*8 + gid][k8 + tig + 4]);
            }
            #pragma unroll
            for (int ni = 0; ni < 4; ni++) mma_tf32(s[ni], af, bf[ni]);
        }

        // ---- causal mask (only diagonal tiles) ----
        const int rq0 = qt*64 + w*16 + gid;       // global q rows
        const int rq1 = rq0 + 8;
        if (kt >= qt*2) {
            #pragma unroll
            for (int ni = 0; ni < 4; ni++) {
                const int c0 = kt*32 + ni*8 + tig*2;
                const int c1 = c0 + 1;
                if (c0 > rq0) s[ni][0] = -INFINITY;
                if (c1 > rq0) s[ni][1] = -INFINITY;
                if (c0 > rq1) s[ni][2] = -INFINITY;
                if (c1 > rq1) s[ni][3] = -INFINITY;
            }
        }

        // ---- online softmax (row reductions across the quad) ----
        float rm0 = -INFINITY, rm1 = -INFINITY;
        #pragma unroll
        for (int ni = 0; ni < 4; ni++) {
            rm0 = fmaxf(rm0, fmaxf(s[ni][0], s[ni][1]));
            rm1 = fmaxf(rm1, fmaxf(s[ni][2], s[ni][3]));
        }
        rm0 = fmaxf(rm0, __shfl_xor_sync(0xffffffffu, rm0, 1));
        rm0 = fmaxf(rm0, __shfl_xor_sync(0xffffffffu, rm0, 2));
        rm1 = fmaxf(rm1, __shfl_xor_sync(0xffffffffu, rm1, 1));
        rm1 = fmaxf(rm1, __shfl_xor_sync(0xffffffffu, rm1, 2));

        const float mn0 = fmaxf(m0r, rm0);
        const float mn1 = fmaxf(m1r, rm1);
        const float sc0 = __expf(m0r - mn0);      // 0 when m0r=-inf
        const float sc1 = __expf(m1r - mn1);
        float rs0 = 0.f, rs1 = 0.f;
        #pragma unroll
        for (int ni = 0; ni < 4; ni++) {
            s[ni][0] = __expf(s[ni][0] - mn0);
            s[ni][1] = __expf(s[ni][1] - mn0);
            s[ni][2] = __expf(s[ni][2] - mn1);
            s[ni][3] = __expf(s[ni][3] - mn1);
            rs0 += s[ni][0] + s[ni][1];
            rs1 += s[ni][2] + s[ni][3];
        }
        rs0 += __shfl_xor_sync(0xffffffffu, rs0, 1);
        rs0 += __shfl_xor_sync(0xffffffffu, rs0, 2);
        rs1 += __shfl_xor_sync(0xffffffffu, rs1, 1);
        rs1 += __shfl_xor_sync(0xffffffffu, rs1, 2);
        l0 = l0 * sc0 + rs0;
        l1 = l1 * sc1 + rs1;
        m0r = mn0; m1r = mn1;
        #pragma unroll
        for (int i = 0; i < 8; i++) {
            o[i][0] *= sc0; o[i][1] *= sc0;
            o[i][2] *= sc1; o[i][3] *= sc1;
        }

        // ---- P -> per-warp smem (tf32-rounded) ----
        #pragma unroll
        for (int ni = 0; ni < 4; ni++) {
            const int c = ni*8 + tig*2;
            ps[w][gid    ][c  ] = __uint_as_float(f2tf32(s[ni][0]));
            ps[w][gid    ][c+1] = __uint_as_float(f2tf32(s[ni][1]));
            ps[w][gid + 8][c  ] = __uint_as_float(f2tf32(s[ni][2]));
            ps[w][gid + 8][c+1] = __uint_as_float(f2tf32(s[ni][3]));
        }
        __syncwarp();

        // ---- O += P V : m16 n64 k32 ----
        #pragma unroll
        for (int k8 = 0; k8 < 32; k8 += 8) {
            uint32_t af[4];
            af[0] = __float_as_uint(ps[w][gid    ][k8 + tig    ]);
            af[1] = __float_as_uint(ps[w][gid + 8][k8 + tig    ]);
            af[2] = __float_as_uint(ps[w][gid    ][k8 + tig + 4]);
            af[3] = __float_as_uint(ps[w][gid + 8][k8 + tig + 4]);
            #pragma unroll
            for (int ni = 0; ni < 8; ni++) {
                uint32_t bf[2];
                bf[0] = __float_as_uint(vs[k8 + tig    ][ni*8 + gid]);
                bf[1] = __float_as_uint(vs[k8 + tig + 4][ni*8 + gid]);
                mma_tf32(o[ni], af, bf);
            }
        }
        __syncwarp();
    }

    // ---- finalize ----
    const float inv0 = 1.f / l0;
    const float inv1 = 1.f / l1;
    const int r0 = base + qt*64 + w*16 + gid;
    const int r1 = r0 + 8;
    #pragma unroll
    for (int ni = 0; ni < 8; ni++) {
        const int c = qcol + ni*8 + tig*2;
        *(float2*)&y[(size_t)r0 * CDIM + c] =
            make_float2(o[ni][0] * inv0, o[ni][1] * inv0);
        *(float2*)&y[(size_t)r1 * CDIM + c] =
            make_float2(o[ni][2] * inv1, o[ni][3] * inv1);
    }
}

// --------------------------------------------------------------------------
// Router / assignment / combine
// --------------------------------------------------------------------------
__global__ void router_kernel(const float* __restrict__ xln2,
                              const float* __restrict__ wg)
{
    __shared__ float wgs[NEXP*CDIM];
    const int tid = threadIdx.x;
    for (int i = tid; i < NEXP*CDIM; i += 256) wgs[i] = wg[i];
    __syncthreads();
    const int lane = tid & 31;
    const int t = blockIdx.x * 8 + (tid >> 5);
    const float* xr = xln2 + (size_t)t * CDIM;
    float xl[24];
    #pragma unroll
    for (int i = 0; i < 24; i++) xl[i] = xr[lane + (i << 5)];
    float lg[8];
    #pragma unroll
    for (int eo = 0; eo < 8; eo++) {
        float acc = 0.f;
        const float* wr = wgs + eo*CDIM;
        #pragma unroll
        for (int i = 0; i < 24; i++) acc = fmaf(xl[i], wr[lane + (i << 5)], acc);
        #pragma unroll
        for (int o = 16; o > 0; o >>= 1) acc += __shfl_down_sync(0xffffffffu, acc, o);
        lg[eo] = acc;
    }
    if (lane == 0) {
        int i1 = 0; float v1 = lg[0];
        #pragma unroll
        for (int eo = 1; eo < 8; eo++) if (lg[eo] > v1) { v1 = lg[eo]; i1 = eo; }
        int i2 = -1; float v2 = -INFINITY;
        #pragma unroll
        for (int eo = 0; eo < 8; eo++)
            if (eo != i1 && lg[eo] > v2) { v2 = lg[eo]; i2 = eo; }
        g_top_idx[t*2]   = i1;
        g_top_idx[t*2+1] = i2;
        g_top_w[t*2]     = 1.f / (1.f + __expf(v2 - v1));
        g_top_w[t*2+1]   = 1.f / (1.f + __expf(v1 - v2));
    }
}

// warp-per-expert ballot/popc greedy assignment (order-exact)
__global__ void assign_kernel()
{
    const int e    = threadIdx.x >> 5;
    const int lane = threadIdx.x & 31;
    int base = 0;
    for (int p0 = 0; p0 < NPAIR; p0 += 32) {
        const int p = p0 + lane;
        const bool match = (g_top_idx[p] == e);
        const unsigned mask = __ballot_sync(0xffffffffu, match);
        if (match) {
            const int pos = base + __popc(mask & ((1u << lane) - 1u));
            if (pos < CAP) {
                g_tok  [(e << 10) + pos] = p >> 1;
                g_pairk[(e << 10) + pos] = p & 1;
                g_wt   [(e << 10) + pos] = g_top_w[p];
            }
        }
        base += __popc(mask);
    }
    if (lane == 0) g_cnt[e] = (base < CAP) ? base : CAP;
}

__global__ void zero_pair_kernel()
{
    const size_t i = (size_t)blockIdx.x * 256 + threadIdx.x;
    g_pair[i] = 0.f;
}

__global__ void combine_kernel(float* __restrict__ out)
{
    const int i = blockIdx.x * 256 + threadIdx.x;
    const int t = i / CDIM;
    const int c = i - t * CDIM;
    out[i] = g_x2[i] + g_pair[(size_t)(t*2)*CDIM + c]
                     + g_pair[(size_t)(t*2 + 1)*CDIM + c];
}

// --------------------------------------------------------------------------
extern "C" void kernel_launch(void* const* d_in, const int* in_sizes, int n_in,
                              void* d_out, int out_size)
{
    const float* x      = (const float*)d_in[0];
    const float* ln1w   = (const float*)d_in[1];
    const float* ln2w   = (const float*)d_in[2];
    const float* cattn  = (const float*)d_in[3];
    const float* cproj  = (const float*)d_in[4];
    const float* wg     = (const float*)d_in[5];
    const float* cfc    = (const float*)d_in[6];
    const float* cproje = (const float*)d_in[7];
    float* out = (float*)d_out;

    float *xln1, *qkv, *attn, *x2, *xln2, *H, *pair, *wt;
    int *tok, *pairk, *cnt;
    cudaGetSymbolAddress((void**)&xln1,  g_xln1);
    cudaGetSymbolAddress((void**)&qkv,   g_qkv);
    cudaGetSymbolAddress((void**)&attn,  g_attn);
    cudaGetSymbolAddress((void**)&x2,    g_x2);
    cudaGetSymbolAddress((void**)&xln2,  g_xln2);
    cudaGetSymbolAddress((void**)&H,     g_H);
    cudaGetSymbolAddress((void**)&pair,  g_pair);
    cudaGetSymbolAddress((void**)&tok,   g_tok);
    cudaGetSymbolAddress((void**)&pairk, g_pairk);
    cudaGetSymbolAddress((void**)&cnt,   g_cnt);
    cudaGetSymbolAddress((void**)&wt,    g_wt);

    ln_kernel<<<NTOK, 256>>>(x, ln1w, xln1);
    gemm_tc_kernel<0><<<dim3(QKVDIM/128, NTOK/128, 1), 256>>>(
        xln1, cattn, qkv, nullptr, CDIM, QKVDIM,
        nullptr, nullptr, nullptr, nullptr);
    attn_tc_kernel<<<dim3(32, 12, 2), 128>>>(qkv, attn);
    gemm_tc_kernel<1><<<dim3(CDIM/128, NTOK/128, 1), 256>>>(
        attn, cproj, x2, x, CDIM, CDIM,
        nullptr, nullptr, nullptr, nullptr);
    ln_kernel<<<NTOK, 256>>>(x2, ln2w, xln2);
    router_kernel<<<NTOK/8, 256>>>(xln2, wg);
    assign_kernel<<<1, 256>>>();
    gemm_tc_kernel<2><<<dim3(FFDIM/128, CAP/128, NEXP), 256>>>(
        xln2, cfc, H, nullptr, CDIM, FFDIM,
        tok, wt, pairk, cnt);
    zero_pair_kernel<<<(NPAIR*CDIM)/256, 256>>>();
    gemm_tc_kernel<3><<<dim3(CDIM/128, CAP/128, NEXP), 256>>>(
        H, cproje, pair, nullptr, FFDIM, CDIM,
        tok, wt, pairk, cnt);
    combine_kernel<<<(NTOK*CDIM)/256, 256>>>(out);
}